// round 3
// baseline (speedup 1.0000x reference)
#include <cuda_runtime.h>
#include <math.h>

#define NN 65536
#define EE 1048576
#define GG 32
#define FH 128
#define CC 40

// ---------------- scratch (device globals; no allocation) ----------------
__device__ __align__(256) float g_hws[(size_t)NN * FH];   // (h @ W) * dinv[row]
__device__ __align__(256) float g_acc[(size_t)NN * FH];   // aggregated output per layer
__device__ __align__(256) float g_Wf[GG * FH * FH];       // fused Wdyn @ conv_w[0]
__device__ __align__(256) int   g_src[EE];
__device__ __align__(256) int   g_dst[EE];
__device__ __align__(256) int   g_deg[NN];
__device__ __align__(256) int   g_rowstart[NN];
__device__ __align__(256) int   g_cursor[NN];
__device__ __align__(256) int   g_sorted[EE];
__device__ __align__(256) float g_dinv[NN];
__device__ int g_is32;

// ---------------- dtype sniff + edge normalization ----------------
// If edge_index is really int32, the 8-byte words contain two node ids and the
// high 32 bits are almost surely nonzero. If int64 (ids < 65536), high bits are 0.
__global__ void detect_k(const unsigned long long* __restrict__ w) {
    if (threadIdx.x == 0) {
        int nz = 0;
        for (int i = 0; i < 64; i++)
            if ((w[i] >> 32) != 0ull) nz++;
        g_is32 = (nz > 8) ? 1 : 0;
    }
}

__global__ void convert_k(const void* __restrict__ ei, int E) {
    int e = blockIdx.x * blockDim.x + threadIdx.x;
    if (e >= E) return;
    if (g_is32) {
        const int* p = (const int*)ei;
        g_src[e] = p[e];
        g_dst[e] = p[E + e];
    } else {
        const long long* p = (const long long*)ei;
        g_src[e] = (int)p[e];
        g_dst[e] = (int)p[(size_t)E + e];
    }
}

// ---------------- degree / CSR build ----------------
__global__ void zero_deg_k() {
    g_deg[blockIdx.x * blockDim.x + threadIdx.x] = 0;
}

__global__ void count_k(int E) {
    int e = blockIdx.x * blockDim.x + threadIdx.x;
    if (e < E) atomicAdd(&g_deg[g_dst[e]], 1);
}

// single-block exclusive scan over 65536 degrees; also writes dinv & cursor
__global__ void scan_k() {
    __shared__ __align__(16) int ps[1024];
    int t = threadIdx.x;
    int base = t * 64;
    int sum = 0;
    for (int i = 0; i < 64; i++) sum += g_deg[base + i];
    ps[t] = sum;
    __syncthreads();
    for (int off = 1; off < 1024; off <<= 1) {
        int v = (t >= off) ? ps[t - off] : 0;
        __syncthreads();
        ps[t] += v;
        __syncthreads();
    }
    int run = ps[t] - sum;   // exclusive prefix for this chunk
    for (int i = 0; i < 64; i++) {
        int d = g_deg[base + i];
        g_rowstart[base + i] = run;
        g_cursor[base + i]   = run;
        g_dinv[base + i]     = rsqrtf((float)(d + 1));  // +1 self loop
        run += d;
    }
}

__global__ void sort_k(int E) {
    int e = blockIdx.x * blockDim.x + threadIdx.x;
    if (e < E) {
        int d = g_dst[e];
        int pos = atomicAdd(&g_cursor[d], 1);
        g_sorted[pos] = g_src[e];
    }
}

// ---------------- Wfused[g] = relu(w0*E_meta + b0) @ conv_w[0] ----------------
__global__ __launch_bounds__(256) void wdyn_fuse_k(
    const float* __restrict__ w0, const float* __restrict__ Em,
    const float* __restrict__ b0, const float* __restrict__ W1)
{
    __shared__ __align__(16) float As[32 * 132];
    __shared__ __align__(16) float Bs[32 * 132];
    int g = blockIdx.x, tid = threadIdx.x;
    int ty = tid >> 4, tx = tid & 15;
    float acc[8][8];
#pragma unroll
    for (int i = 0; i < 8; i++)
#pragma unroll
        for (int j = 0; j < 8; j++) acc[i][j] = 0.f;

#pragma unroll 1
    for (int k0 = 0; k0 < 128; k0 += 32) {
        int c4 = (tid & 7) * 4;
#pragma unroll
        for (int it = 0; it < 4; it++) {
            int r = (tid >> 3) + it * 32;   // f
            float wv = w0[r];
            float4 em = *(const float4*)&Em[g * 128 + k0 + c4];
            float4 bb = *(const float4*)&b0[r * 128 + k0 + c4];
            As[(c4 + 0) * 132 + r] = fmaxf(fmaf(wv, em.x, bb.x), 0.f);
            As[(c4 + 1) * 132 + r] = fmaxf(fmaf(wv, em.y, bb.y), 0.f);
            As[(c4 + 2) * 132 + r] = fmaxf(fmaf(wv, em.z, bb.z), 0.f);
            As[(c4 + 3) * 132 + r] = fmaxf(fmaf(wv, em.w, bb.w), 0.f);
        }
#pragma unroll
        for (int it = 0; it < 4; it++) {
            int idx = it * 256 + tid;
            int r = idx >> 5, cc = (idx & 31) * 4;
            *(float4*)&Bs[r * 132 + cc] = *(const float4*)&W1[(k0 + r) * 128 + cc];
        }
        __syncthreads();
#pragma unroll 8
        for (int kk = 0; kk < 32; kk++) {
            float a[8], b[8];
            *(float4*)&a[0] = *(const float4*)&As[kk * 132 + ty * 8];
            *(float4*)&a[4] = *(const float4*)&As[kk * 132 + ty * 8 + 4];
            *(float4*)&b[0] = *(const float4*)&Bs[kk * 132 + tx * 8];
            *(float4*)&b[4] = *(const float4*)&Bs[kk * 132 + tx * 8 + 4];
#pragma unroll
            for (int i = 0; i < 8; i++)
#pragma unroll
                for (int j = 0; j < 8; j++) acc[i][j] = fmaf(a[i], b[j], acc[i][j]);
        }
        __syncthreads();
    }
#pragma unroll
    for (int i = 0; i < 8; i++) {
        int row = ty * 8 + i;
        float4 o0 = make_float4(acc[i][0], acc[i][1], acc[i][2], acc[i][3]);
        float4 o1 = make_float4(acc[i][4], acc[i][5], acc[i][6], acc[i][7]);
        *(float4*)&g_Wf[g * 16384 + row * 128 + tx * 8]     = o0;
        *(float4*)&g_Wf[g * 16384 + row * 128 + tx * 8 + 4] = o1;
    }
}

// ---------------- main GEMM: hws = relu(A + bias) @ B * dinv[row] ----------------
// useAcc: A = g_acc (internal); perGroupB: B = g_Wf + group*16K
__global__ __launch_bounds__(256) void gemm128_k(
    const float* __restrict__ Aext, const float* __restrict__ Bext,
    const float* __restrict__ bias, int useAcc, int perGroupB)
{
    __shared__ __align__(16) float As[32 * 132];
    __shared__ __align__(16) float Bs[32 * 132];
    int tid = threadIdx.x;
    int m0 = blockIdx.x * 128;
    const float* A = useAcc ? g_acc : Aext;
    const float* B = perGroupB ? (g_Wf + (m0 >> 11) * (FH * FH)) : Bext;
    int ty = tid >> 4, tx = tid & 15;
    float acc[8][8];
#pragma unroll
    for (int i = 0; i < 8; i++)
#pragma unroll
        for (int j = 0; j < 8; j++) acc[i][j] = 0.f;

#pragma unroll 1
    for (int k0 = 0; k0 < 128; k0 += 32) {
        int c4 = (tid & 7) * 4;
#pragma unroll
        for (int it = 0; it < 4; it++) {
            int r = (tid >> 3) + it * 32;
            float4 v = *(const float4*)&A[(size_t)(m0 + r) * FH + k0 + c4];
            if (bias) {
                float4 bb = *(const float4*)&bias[k0 + c4];
                v.x = fmaxf(v.x + bb.x, 0.f);
                v.y = fmaxf(v.y + bb.y, 0.f);
                v.z = fmaxf(v.z + bb.z, 0.f);
                v.w = fmaxf(v.w + bb.w, 0.f);
            }
            As[(c4 + 0) * 132 + r] = v.x;
            As[(c4 + 1) * 132 + r] = v.y;
            As[(c4 + 2) * 132 + r] = v.z;
            As[(c4 + 3) * 132 + r] = v.w;
        }
#pragma unroll
        for (int it = 0; it < 4; it++) {
            int idx = it * 256 + tid;
            int r = idx >> 5, cc = (idx & 31) * 4;
            *(float4*)&Bs[r * 132 + cc] = *(const float4*)&B[(k0 + r) * FH + cc];
        }
        __syncthreads();
#pragma unroll 8
        for (int kk = 0; kk < 32; kk++) {
            float a[8], b[8];
            *(float4*)&a[0] = *(const float4*)&As[kk * 132 + ty * 8];
            *(float4*)&a[4] = *(const float4*)&As[kk * 132 + ty * 8 + 4];
            *(float4*)&b[0] = *(const float4*)&Bs[kk * 132 + tx * 8];
            *(float4*)&b[4] = *(const float4*)&Bs[kk * 132 + tx * 8 + 4];
#pragma unroll
            for (int i = 0; i < 8; i++)
#pragma unroll
                for (int j = 0; j < 8; j++) acc[i][j] = fmaf(a[i], b[j], acc[i][j]);
        }
        __syncthreads();
    }
#pragma unroll
    for (int i = 0; i < 8; i++) {
        int r = m0 + ty * 8 + i;
        float d = g_dinv[r];
        float4 o0 = make_float4(acc[i][0] * d, acc[i][1] * d, acc[i][2] * d, acc[i][3] * d);
        float4 o1 = make_float4(acc[i][4] * d, acc[i][5] * d, acc[i][6] * d, acc[i][7] * d);
        *(float4*)&g_hws[(size_t)r * FH + tx * 8]     = o0;
        *(float4*)&g_hws[(size_t)r * FH + tx * 8 + 4] = o1;
    }
}

// ---------------- CSR aggregate: acc[n] = dinv[n]*(hws[n] + sum_src hws[src]) ----------------
__global__ __launch_bounds__(256) void agg_k() {
    int warp = (blockIdx.x * 256 + threadIdx.x) >> 5;
    int lane = threadIdx.x & 31;
    const float4* hv = (const float4*)g_hws;
    float4 a = hv[(size_t)warp * 32 + lane];   // self loop term
    int s0 = g_rowstart[warp];
    int dn = g_deg[warp];
    int e = 0;
    for (; e + 2 <= dn; e += 2) {
        int i1 = g_sorted[s0 + e];
        int i2 = g_sorted[s0 + e + 1];
        float4 v1 = hv[(size_t)i1 * 32 + lane];
        float4 v2 = hv[(size_t)i2 * 32 + lane];
        a.x += v1.x + v2.x; a.y += v1.y + v2.y;
        a.z += v1.z + v2.z; a.w += v1.w + v2.w;
    }
    if (e < dn) {
        int i1 = g_sorted[s0 + e];
        float4 v1 = hv[(size_t)i1 * 32 + lane];
        a.x += v1.x; a.y += v1.y; a.z += v1.z; a.w += v1.w;
    }
    float d = g_dinv[warp];
    a.x *= d; a.y *= d; a.z *= d; a.w *= d;
    ((float4*)g_acc)[(size_t)warp * 32 + lane] = a;
}

// ---------------- logits + log_softmax ----------------
__global__ __launch_bounds__(256) void logits_k(
    const float* __restrict__ bias, const float* __restrict__ W,
    const float* __restrict__ lb, float* __restrict__ out)
{
    __shared__ __align__(16) float Ws[64 * 129];   // padded rows; rows 40..63 unused
    __shared__ __align__(16) float Hs[8 * 128];
    int tid = threadIdx.x;
    for (int i = tid; i < CC * 128; i += 256) {
        int c = i >> 7, k = i & 127;
        Ws[c * 129 + k] = W[i];
    }
    // zero the unused rows so uninitialized reads are benign
    for (int i = CC * 128 + tid; i < 64 * 128; i += 256) {
        int c = i >> 7, k = i & 127;
        Ws[c * 129 + k] = 0.f;
    }
    __syncthreads();
    int wl = tid >> 5;
    int lane = tid & 31;
    int node = blockIdx.x * 8 + wl;
    float4 h = ((const float4*)g_acc)[(size_t)node * 32 + lane];
    float4 bb = ((const float4*)bias)[lane];
    h.x = fmaxf(h.x + bb.x, 0.f);
    h.y = fmaxf(h.y + bb.y, 0.f);
    h.z = fmaxf(h.z + bb.z, 0.f);
    h.w = fmaxf(h.w + bb.w, 0.f);
    *(float4*)&Hs[wl * 128 + lane * 4] = h;
    __syncwarp();
    float s0 = lb[lane];
    float s1 = (lane < 8) ? lb[32 + lane] : 0.f;
    const float* hrow = &Hs[wl * 128];
    const float* wr0 = &Ws[lane * 129];
    const float* wr1 = &Ws[(32 + lane) * 129];
#pragma unroll 8
    for (int k = 0; k < 128; k++) {
        float hvv = hrow[k];
        s0 = fmaf(hvv, wr0[k], s0);
        s1 = fmaf(hvv, wr1[k], s1);
    }
    float m = (lane < 8) ? fmaxf(s0, s1) : s0;
#pragma unroll
    for (int off = 16; off; off >>= 1) m = fmaxf(m, __shfl_xor_sync(0xffffffffu, m, off));
    float e0 = expf(s0 - m);
    float e1 = (lane < 8) ? expf(s1 - m) : 0.f;
    float es = e0 + e1;
#pragma unroll
    for (int off = 16; off; off >>= 1) es += __shfl_xor_sync(0xffffffffu, es, off);
    float lse = m + logf(es);
    out[(size_t)node * CC + lane] = s0 - lse;
    if (lane < 8) out[(size_t)node * CC + 32 + lane] = s1 - lse;
}

// ---------------- launch ----------------
extern "C" void kernel_launch(void* const* d_in, const int* in_sizes, int n_in,
                              void* d_out, int out_size) {
    const float* x     = (const float*)d_in[0];
    const void*  ei    = d_in[1];
    const float* Em    = (const float*)d_in[2];
    const float* w0    = (const float*)d_in[4];
    const float* b0    = (const float*)d_in[5];
    const float* convw = (const float*)d_in[6];
    const float* convb = (const float*)d_in[7];
    const float* ltw   = (const float*)d_in[8];
    const float* ltb   = (const float*)d_in[9];
    float* out = (float*)d_out;
    int E = in_sizes[1] / 2;

    // edge dtype sniff (int32 vs int64) + normalize to int32 src/dst
    detect_k<<<1, 32>>>((const unsigned long long*)ei);
    convert_k<<<(E + 255) / 256, 256>>>(ei, E);

    // CSR build (depends only on edge_index)
    zero_deg_k<<<NN / 256, 256>>>();
    count_k<<<(E + 255) / 256, 256>>>(E);
    scan_k<<<1, 1024>>>();
    sort_k<<<(E + 255) / 256, 256>>>(E);

    // Wfused = relu(w0*E_meta + b0) @ conv_w[0]
    wdyn_fuse_k<<<GG, 256>>>(w0, Em, b0, convw);

    // layer 1: hw1 = x @ Wfused[g], scaled by dinv
    gemm128_k<<<NN / 128, 256>>>(x, nullptr, nullptr, 0, 1);
    agg_k<<<NN / 8, 256>>>();
    // layer 2: hw2 = relu(acc + b0) @ W2
    gemm128_k<<<NN / 128, 256>>>(nullptr, convw + 1 * FH * FH, convb + 0 * FH, 1, 0);
    agg_k<<<NN / 8, 256>>>();
    // layer 3: hw3 = relu(acc + b1) @ W3
    gemm128_k<<<NN / 128, 256>>>(nullptr, convw + 2 * FH * FH, convb + 1 * FH, 1, 0);
    agg_k<<<NN / 8, 256>>>();
    // logits + log_softmax from relu(acc + b2)
    logits_k<<<NN / 8, 256>>>(convb + 2 * FH, ltw, ltb, out);
}

// round 5
// speedup vs baseline: 1.2609x; 1.2609x over previous
#include <cuda_runtime.h>
#include <math.h>

#define NN 65536
#define EE 1048576
#define GG 32
#define FH 128
#define CC 40

// ---------------- scratch (device globals; no allocation) ----------------
__device__ __align__(256) float g_hws[(size_t)NN * FH];   // (h @ W) * dinv[row]
__device__ __align__(256) float g_acc[(size_t)NN * FH];   // aggregated output per layer
__device__ __align__(256) float g_Wf[GG * FH * FH];       // fused Wdyn @ conv_w[0]
__device__ __align__(256) int   g_src[EE];
__device__ __align__(256) int   g_dst[EE];
__device__ __align__(256) int   g_deg[NN];
__device__ __align__(256) int   g_rowstart[NN];
__device__ __align__(256) int   g_cursor[NN];
__device__ __align__(256) int   g_sorted[EE];
__device__ __align__(256) float g_dinv[NN];
__device__ int g_is32;

__device__ __forceinline__ unsigned tf32r(float x) {
    unsigned u;
    asm("cvt.rna.tf32.f32 %0, %1;" : "=r"(u) : "f"(x));
    return u;
}

// ---------------- dtype sniff + edge normalization (+ degree count) ----------------
__global__ void detect_k(const unsigned long long* __restrict__ w) {
    if (threadIdx.x == 0) {
        int nz = 0;
        for (int i = 0; i < 64; i++)
            if ((w[i] >> 32) != 0ull) nz++;
        g_is32 = (nz > 8) ? 1 : 0;
    }
}

__global__ void zero_deg_k() {
    g_deg[blockIdx.x * blockDim.x + threadIdx.x] = 0;
}

__global__ void conv_count_k(const void* __restrict__ ei, int E) {
    int e = blockIdx.x * blockDim.x + threadIdx.x;
    if (e >= E) return;
    int s, d;
    if (g_is32) {
        const int* p = (const int*)ei;
        s = p[e];
        d = p[E + e];
    } else {
        const long long* p = (const long long*)ei;
        s = (int)p[e];
        d = (int)p[(size_t)E + e];
    }
    g_src[e] = s;
    g_dst[e] = d;
    atomicAdd(&g_deg[d], 1);
}

// single-block exclusive scan over 65536 degrees; also writes dinv & cursor
__global__ void scan_k() {
    __shared__ __align__(16) int ps[1024];
    int t = threadIdx.x;
    int base = t * 64;
    int sum = 0;
    for (int i = 0; i < 64; i++) sum += g_deg[base + i];
    ps[t] = sum;
    __syncthreads();
    for (int off = 1; off < 1024; off <<= 1) {
        int v = (t >= off) ? ps[t - off] : 0;
        __syncthreads();
        ps[t] += v;
        __syncthreads();
    }
    int run = ps[t] - sum;   // exclusive prefix for this chunk
    for (int i = 0; i < 64; i++) {
        int d = g_deg[base + i];
        g_rowstart[base + i] = run;
        g_cursor[base + i]   = run;
        g_dinv[base + i]     = rsqrtf((float)(d + 1));  // +1 self loop
        run += d;
    }
}

__global__ void sort_k(int E) {
    int e = blockIdx.x * blockDim.x + threadIdx.x;
    if (e < E) {
        int d = g_dst[e];
        int pos = atomicAdd(&g_cursor[d], 1);
        g_sorted[pos] = g_src[e];
    }
}

// ---------------- Wfused[g] = relu(w0*E_meta + b0) @ conv_w[0] ----------------
__global__ __launch_bounds__(256) void wdyn_fuse_k(
    const float* __restrict__ w0, const float* __restrict__ Em,
    const float* __restrict__ b0, const float* __restrict__ W1)
{
    __shared__ __align__(16) float As[32 * 132];
    __shared__ __align__(16) float Bs[32 * 132];
    int g = blockIdx.x, tid = threadIdx.x;
    int ty = tid >> 4, tx = tid & 15;
    float acc[8][8];
#pragma unroll
    for (int i = 0; i < 8; i++)
#pragma unroll
        for (int j = 0; j < 8; j++) acc[i][j] = 0.f;

#pragma unroll 1
    for (int k0 = 0; k0 < 128; k0 += 32) {
        int c4 = (tid & 7) * 4;
#pragma unroll
        for (int it = 0; it < 4; it++) {
            int r = (tid >> 3) + it * 32;   // f
            float wv = w0[r];
            float4 em = *(const float4*)&Em[g * 128 + k0 + c4];
            float4 bb = *(const float4*)&b0[r * 128 + k0 + c4];
            As[(c4 + 0) * 132 + r] = fmaxf(fmaf(wv, em.x, bb.x), 0.f);
            As[(c4 + 1) * 132 + r] = fmaxf(fmaf(wv, em.y, bb.y), 0.f);
            As[(c4 + 2) * 132 + r] = fmaxf(fmaf(wv, em.z, bb.z), 0.f);
            As[(c4 + 3) * 132 + r] = fmaxf(fmaf(wv, em.w, bb.w), 0.f);
        }
#pragma unroll
        for (int it = 0; it < 4; it++) {
            int idx = it * 256 + tid;
            int r = idx >> 5, cc = (idx & 31) * 4;
            *(float4*)&Bs[r * 132 + cc] = *(const float4*)&W1[(k0 + r) * 128 + cc];
        }
        __syncthreads();
#pragma unroll 8
        for (int kk = 0; kk < 32; kk++) {
            float a[8], b[8];
            *(float4*)&a[0] = *(const float4*)&As[kk * 132 + ty * 8];
            *(float4*)&a[4] = *(const float4*)&As[kk * 132 + ty * 8 + 4];
            *(float4*)&b[0] = *(const float4*)&Bs[kk * 132 + tx * 8];
            *(float4*)&b[4] = *(const float4*)&Bs[kk * 132 + tx * 8 + 4];
#pragma unroll
            for (int i = 0; i < 8; i++)
#pragma unroll
                for (int j = 0; j < 8; j++) acc[i][j] = fmaf(a[i], b[j], acc[i][j]);
        }
        __syncthreads();
    }
#pragma unroll
    for (int i = 0; i < 8; i++) {
        int row = ty * 8 + i;
        float4 o0 = make_float4(acc[i][0], acc[i][1], acc[i][2], acc[i][3]);
        float4 o1 = make_float4(acc[i][4], acc[i][5], acc[i][6], acc[i][7]);
        *(float4*)&g_Wf[g * 16384 + row * 128 + tx * 8]     = o0;
        *(float4*)&g_Wf[g * 16384 + row * 128 + tx * 8 + 4] = o1;
    }
}

// ---------------- TF32 tensor-core GEMM: hws = relu(A + bias) @ B * dinv[row] ----------------
// 8 warps per CTA; warp w computes rows [m0 + 16w, m0 + 16w + 16) x all 128 cols.
__global__ __launch_bounds__(256, 2) void gemm_tc_k(
    const float* __restrict__ Aext, const float* __restrict__ Bext,
    const float* __restrict__ bias, int useAcc, int perGroupB)
{
    __shared__ __align__(16) float As[128 * 36];
    __shared__ __align__(16) float Bs[32 * 132];
    int tid = threadIdx.x;
    int m0 = blockIdx.x * 128;
    const float* A = useAcc ? g_acc : Aext;
    const float* B = perGroupB ? (g_Wf + (m0 >> 11) * (FH * FH)) : Bext;
    int wid = tid >> 5, lane = tid & 31;
    int g = lane >> 2, t = lane & 3;

    float c[16][4];
#pragma unroll
    for (int nt = 0; nt < 16; nt++)
#pragma unroll
        for (int j = 0; j < 4; j++) c[nt][j] = 0.f;

#pragma unroll 1
    for (int k0 = 0; k0 < 128; k0 += 32) {
        // stage A chunk [128 x 32] -> As (pad 36): 1024 float4s over 256 threads = 4 iters
#pragma unroll
        for (int it = 0; it < 4; it++) {
            int i = it * 256 + tid;
            int r = i >> 3, c4 = (i & 7) * 4;     // r in [0,128), c4 in {0,4,...,28}
            float4 v = *(const float4*)&A[(size_t)(m0 + r) * FH + k0 + c4];
            if (bias) {
                float4 bb = *(const float4*)&bias[k0 + c4];
                v.x = fmaxf(v.x + bb.x, 0.f);
                v.y = fmaxf(v.y + bb.y, 0.f);
                v.z = fmaxf(v.z + bb.z, 0.f);
                v.w = fmaxf(v.w + bb.w, 0.f);
            }
            As[r * 36 + c4 + 0] = __uint_as_float(tf32r(v.x));
            As[r * 36 + c4 + 1] = __uint_as_float(tf32r(v.y));
            As[r * 36 + c4 + 2] = __uint_as_float(tf32r(v.z));
            As[r * 36 + c4 + 3] = __uint_as_float(tf32r(v.w));
        }
        // stage B chunk [32 x 128] -> Bs (pad 132): 1024 float4s = 4 iters
#pragma unroll
        for (int it = 0; it < 4; it++) {
            int i = it * 256 + tid;
            int r = i >> 5, cc = (i & 31) * 4;    // r in [0,32), cc in {0,...,124}
            float4 v = *(const float4*)&B[(k0 + r) * FH + cc];
            Bs[r * 132 + cc + 0] = __uint_as_float(tf32r(v.x));
            Bs[r * 132 + cc + 1] = __uint_as_float(tf32r(v.y));
            Bs[r * 132 + cc + 2] = __uint_as_float(tf32r(v.z));
            Bs[r * 132 + cc + 3] = __uint_as_float(tf32r(v.w));
        }
        __syncthreads();
#pragma unroll
        for (int kk = 0; kk < 32; kk += 8) {
            int ar = (wid * 16 + g) * 36 + kk + t;
            unsigned a0 = __float_as_uint(As[ar]);
            unsigned a1 = __float_as_uint(As[ar + 8 * 36]);
            unsigned a2 = __float_as_uint(As[ar + 4]);
            unsigned a3 = __float_as_uint(As[ar + 8 * 36 + 4]);
#pragma unroll
            for (int nt = 0; nt < 16; nt++) {
                unsigned b0 = __float_as_uint(Bs[(kk + t) * 132 + nt * 8 + g]);
                unsigned b1 = __float_as_uint(Bs[(kk + t + 4) * 132 + nt * 8 + g]);
                asm volatile(
                    "mma.sync.aligned.m16n8k8.row.col.f32.tf32.tf32.f32 "
                    "{%0,%1,%2,%3}, {%4,%5,%6,%7}, {%8,%9}, {%0,%1,%2,%3};"
                    : "+f"(c[nt][0]), "+f"(c[nt][1]), "+f"(c[nt][2]), "+f"(c[nt][3])
                    : "r"(a0), "r"(a1), "r"(a2), "r"(a3), "r"(b0), "r"(b1));
            }
        }
        __syncthreads();
    }

    int r0 = m0 + wid * 16 + g;
    float d0 = g_dinv[r0];
    float d1 = g_dinv[r0 + 8];
#pragma unroll
    for (int nt = 0; nt < 16; nt++) {
        int col = nt * 8 + 2 * t;
        *(float2*)&g_hws[(size_t)r0 * FH + col] =
            make_float2(c[nt][0] * d0, c[nt][1] * d0);
        *(float2*)&g_hws[(size_t)(r0 + 8) * FH + col] =
            make_float2(c[nt][2] * d1, c[nt][3] * d1);
    }
}

// ---------------- CSR aggregate: acc[n] = dinv[n]*(hws[n] + sum_src hws[src]) ----------------
__global__ __launch_bounds__(256) void agg_k() {
    int warp = (blockIdx.x * 256 + threadIdx.x) >> 5;
    int lane = threadIdx.x & 31;
    const float4* hv = (const float4*)g_hws;
    float4 a = hv[(size_t)warp * 32 + lane];   // self loop term
    int s0 = g_rowstart[warp];
    int dn = g_deg[warp];
    int e = 0;
    for (; e + 2 <= dn; e += 2) {
        int i1 = g_sorted[s0 + e];
        int i2 = g_sorted[s0 + e + 1];
        float4 v1 = hv[(size_t)i1 * 32 + lane];
        float4 v2 = hv[(size_t)i2 * 32 + lane];
        a.x += v1.x + v2.x; a.y += v1.y + v2.y;
        a.z += v1.z + v2.z; a.w += v1.w + v2.w;
    }
    if (e < dn) {
        int i1 = g_sorted[s0 + e];
        float4 v1 = hv[(size_t)i1 * 32 + lane];
        a.x += v1.x; a.y += v1.y; a.z += v1.z; a.w += v1.w;
    }
    float d = g_dinv[warp];
    a.x *= d; a.y *= d; a.z *= d; a.w *= d;
    ((float4*)g_acc)[(size_t)warp * 32 + lane] = a;
}

// ---------------- logits + log_softmax (32 nodes per block) ----------------
__global__ __launch_bounds__(256) void logits_k(
    const float* __restrict__ bias, const float* __restrict__ W,
    const float* __restrict__ lb, float* __restrict__ out)
{
    __shared__ __align__(16) float Ws[64 * 129];   // padded rows; rows 40..63 zeroed
    __shared__ __align__(16) float Hs[8 * 128];
    int tid = threadIdx.x;
    for (int i = tid; i < CC * 128; i += 256) {
        int cI = i >> 7, k = i & 127;
        Ws[cI * 129 + k] = W[i];
    }
    for (int i = CC * 128 + tid; i < 64 * 128; i += 256) {
        int cI = i >> 7, k = i & 127;
        Ws[cI * 129 + k] = 0.f;
    }
    __syncthreads();
    int wl = tid >> 5;
    int lane = tid & 31;
    float4 bb = ((const float4*)bias)[lane];
    float lb0 = lb[lane];
    float lb1 = (lane < 8) ? lb[32 + lane] : 0.f;
    const float* hrow = &Hs[wl * 128];
    const float* wr0 = &Ws[lane * 129];
    const float* wr1 = &Ws[(32 + lane) * 129];

#pragma unroll 1
    for (int rep = 0; rep < 4; rep++) {
        int node = blockIdx.x * 32 + wl * 4 + rep;
        float4 h = ((const float4*)g_acc)[(size_t)node * 32 + lane];
        h.x = fmaxf(h.x + bb.x, 0.f);
        h.y = fmaxf(h.y + bb.y, 0.f);
        h.z = fmaxf(h.z + bb.z, 0.f);
        h.w = fmaxf(h.w + bb.w, 0.f);
        *(float4*)&Hs[wl * 128 + lane * 4] = h;
        __syncwarp();
        float s0 = lb0;
        float s1 = lb1;
#pragma unroll 8
        for (int k = 0; k < 128; k++) {
            float hvv = hrow[k];
            s0 = fmaf(hvv, wr0[k], s0);
            s1 = fmaf(hvv, wr1[k], s1);
        }
        float m = (lane < 8) ? fmaxf(s0, s1) : s0;
#pragma unroll
        for (int off = 16; off; off >>= 1) m = fmaxf(m, __shfl_xor_sync(0xffffffffu, m, off));
        float e0 = expf(s0 - m);
        float e1 = (lane < 8) ? expf(s1 - m) : 0.f;
        float es = e0 + e1;
#pragma unroll
        for (int off = 16; off; off >>= 1) es += __shfl_xor_sync(0xffffffffu, es, off);
        float lse = m + logf(es);
        out[(size_t)node * CC + lane] = s0 - lse;
        if (lane < 8) out[(size_t)node * CC + 32 + lane] = s1 - lse;
        __syncwarp();
    }
}

// ---------------- launch ----------------
extern "C" void kernel_launch(void* const* d_in, const int* in_sizes, int n_in,
                              void* d_out, int out_size) {
    const float* x     = (const float*)d_in[0];
    const void*  ei    = d_in[1];
    const float* Em    = (const float*)d_in[2];
    const float* w0    = (const float*)d_in[4];
    const float* b0    = (const float*)d_in[5];
    const float* convw = (const float*)d_in[6];
    const float* convb = (const float*)d_in[7];
    const float* ltw   = (const float*)d_in[8];
    const float* ltb   = (const float*)d_in[9];
    float* out = (float*)d_out;
    int E = in_sizes[1] / 2;

    // edge dtype sniff (int32 vs int64) + normalize + degree count
    detect_k<<<1, 32>>>((const unsigned long long*)ei);
    zero_deg_k<<<NN / 256, 256>>>();
    conv_count_k<<<(E + 255) / 256, 256>>>(ei, E);
    scan_k<<<1, 1024>>>();
    sort_k<<<(E + 255) / 256, 256>>>(E);

    // Wfused = relu(w0*E_meta + b0) @ conv_w[0]
    wdyn_fuse_k<<<GG, 256>>>(w0, Em, b0, convw);

    // layer 1: hw1 = x @ Wfused[g], scaled by dinv
    gemm_tc_k<<<NN / 128, 256>>>(x, nullptr, nullptr, 0, 1);
    agg_k<<<NN / 8, 256>>>();
    // layer 2: hw2 = relu(acc + b0) @ W2
    gemm_tc_k<<<NN / 128, 256>>>(nullptr, convw + 1 * FH * FH, convb + 0 * FH, 1, 0);
    agg_k<<<NN / 8, 256>>>();
    // layer 3: hw3 = relu(acc + b1) @ W3
    gemm_tc_k<<<NN / 128, 256>>>(nullptr, convw + 2 * FH * FH, convb + 1 * FH, 1, 0);
    agg_k<<<NN / 8, 256>>>();
    // logits + log_softmax from relu(acc + b2)
    logits_k<<<NN / 32, 256>>>(convb + 2 * FH, ltw, ltb, out);
}

// round 9
// speedup vs baseline: 1.4550x; 1.1540x over previous
#include <cuda_runtime.h>
#include <cuda_fp16.h>
#include <math.h>

#define NN 65536
#define EE 1048576
#define GG 32
#define FH 128
#define CC 40

// ---------------- scratch (device globals; no allocation) ----------------
__device__ __align__(256) __half g_hwsh[(size_t)NN * FH]; // (h @ W) * dinv[row], fp16
__device__ __align__(256) float g_acc[(size_t)NN * FH];   // aggregated output per layer
__device__ __align__(256) float g_Wf[GG * FH * FH];       // fused Wdyn @ conv_w[0]
__device__ __align__(256) int   g_src[EE];
__device__ __align__(256) int   g_dst[EE];
__device__ __align__(256) int   g_deg[NN];
__device__ __align__(256) int   g_rowstart[NN];
__device__ __align__(256) int   g_cursor[NN];
__device__ __align__(256) int   g_sorted[EE];
__device__ __align__(256) float g_dinv[NN];
__device__ __align__(256) int   g_bsum[256];
__device__ int g_is32;

__device__ __forceinline__ unsigned tf32r(float x) {
    unsigned u;
    asm("cvt.rna.tf32.f32 %0, %1;" : "=r"(u) : "f"(x));
    return u;
}

// ---------------- dtype sniff + edge normalization (+ degree count) ----------------
__global__ void detect_k(const unsigned long long* __restrict__ w) {
    if (threadIdx.x == 0) {
        int nz = 0;
        for (int i = 0; i < 64; i++)
            if ((w[i] >> 32) != 0ull) nz++;
        g_is32 = (nz > 8) ? 1 : 0;
    }
}

__global__ void zero_deg_k() {
    g_deg[blockIdx.x * blockDim.x + threadIdx.x] = 0;
}

__global__ void conv_count_k(const void* __restrict__ ei, int E) {
    int e = blockIdx.x * blockDim.x + threadIdx.x;
    if (e >= E) return;
    int s, d;
    if (g_is32) {
        const int* p = (const int*)ei;
        s = p[e];
        d = p[E + e];
    } else {
        const long long* p = (const long long*)ei;
        s = (int)p[e];
        d = (int)p[(size_t)E + e];
    }
    g_src[e] = s;
    g_dst[e] = d;
    atomicAdd(&g_deg[d], 1);
}

// ---------------- parallel 3-phase exclusive scan over degrees ----------------
// phase 1: per-block (256 elems) scan, write local exclusive prefix + dinv + block sum
__global__ __launch_bounds__(256) void scan1_k() {
    __shared__ int ws[8];
    int t = threadIdx.x;
    int i = blockIdx.x * 256 + t;
    int d = g_deg[i];
    int lane = t & 31, w = t >> 5;
    int inc = d;
#pragma unroll
    for (int off = 1; off < 32; off <<= 1) {
        int v = __shfl_up_sync(0xffffffffu, inc, off);
        if (lane >= off) inc += v;
    }
    if (lane == 31) ws[w] = inc;
    __syncthreads();
    if (t < 8) {
        int v = ws[t];
        int s = v;
#pragma unroll
        for (int off = 1; off < 8; off <<= 1) {
            int u = __shfl_up_sync(0xffu, s, off, 8);
            if (t >= off) s += u;
        }
        ws[t] = s - v;   // exclusive warp offset
    }
    __syncthreads();
    int ex = inc - d + ws[w];
    g_rowstart[i] = ex;
    g_dinv[i] = rsqrtf((float)(d + 1));  // +1 self loop
    if (t == 255) g_bsum[blockIdx.x] = ex + d;
}

// phase 2: single block, exclusive scan of 256 block sums (in place)
__global__ __launch_bounds__(256) void scan2_k() {
    __shared__ int ws[8];
    int t = threadIdx.x;
    int d = g_bsum[t];
    int lane = t & 31, w = t >> 5;
    int inc = d;
#pragma unroll
    for (int off = 1; off < 32; off <<= 1) {
        int v = __shfl_up_sync(0xffffffffu, inc, off);
        if (lane >= off) inc += v;
    }
    if (lane == 31) ws[w] = inc;
    __syncthreads();
    if (t < 8) {
        int v = ws[t];
        int s = v;
#pragma unroll
        for (int off = 1; off < 8; off <<= 1) {
            int u = __shfl_up_sync(0xffu, s, off, 8);
            if (t >= off) s += u;
        }
        ws[t] = s - v;
    }
    __syncthreads();
    g_bsum[t] = inc - d + ws[w];
}

// phase 3: add block offsets, init cursor
__global__ __launch_bounds__(256) void scan3_k() {
    int i = blockIdx.x * 256 + threadIdx.x;
    int v = g_rowstart[i] + g_bsum[blockIdx.x];
    g_rowstart[i] = v;
    g_cursor[i] = v;
}

__global__ void sort_k(int E) {
    int e = blockIdx.x * blockDim.x + threadIdx.x;
    if (e < E) {
        int d = g_dst[e];
        int pos = atomicAdd(&g_cursor[d], 1);
        g_sorted[pos] = g_src[e];
    }
}

// ---------------- Wfused[g] = relu(w0*E_meta + b0) @ conv_w[0] ----------------
__global__ __launch_bounds__(256) void wdyn_fuse_k(
    const float* __restrict__ w0, const float* __restrict__ Em,
    const float* __restrict__ b0, const float* __restrict__ W1)
{
    __shared__ __align__(16) float As[32 * 132];
    __shared__ __align__(16) float Bs[32 * 132];
    int g = blockIdx.x, tid = threadIdx.x;
    int ty = tid >> 4, tx = tid & 15;
    float acc[8][8];
#pragma unroll
    for (int i = 0; i < 8; i++)
#pragma unroll
        for (int j = 0; j < 8; j++) acc[i][j] = 0.f;

#pragma unroll 1
    for (int k0 = 0; k0 < 128; k0 += 32) {
        int c4 = (tid & 7) * 4;
#pragma unroll
        for (int it = 0; it < 4; it++) {
            int r = (tid >> 3) + it * 32;   // f
            float wv = w0[r];
            float4 em = *(const float4*)&Em[g * 128 + k0 + c4];
            float4 bb = *(const float4*)&b0[r * 128 + k0 + c4];
            As[(c4 + 0) * 132 + r] = fmaxf(fmaf(wv, em.x, bb.x), 0.f);
            As[(c4 + 1) * 132 + r] = fmaxf(fmaf(wv, em.y, bb.y), 0.f);
            As[(c4 + 2) * 132 + r] = fmaxf(fmaf(wv, em.z, bb.z), 0.f);
            As[(c4 + 3) * 132 + r] = fmaxf(fmaf(wv, em.w, bb.w), 0.f);
        }
#pragma unroll
        for (int it = 0; it < 4; it++) {
            int idx = it * 256 + tid;
            int r = idx >> 5, cc = (idx & 31) * 4;
            *(float4*)&Bs[r * 132 + cc] = *(const float4*)&W1[(k0 + r) * 128 + cc];
        }
        __syncthreads();
#pragma unroll 8
        for (int kk = 0; kk < 32; kk++) {
            float a[8], b[8];
            *(float4*)&a[0] = *(const float4*)&As[kk * 132 + ty * 8];
            *(float4*)&a[4] = *(const float4*)&As[kk * 132 + ty * 8 + 4];
            *(float4*)&b[0] = *(const float4*)&Bs[kk * 132 + tx * 8];
            *(float4*)&b[4] = *(const float4*)&Bs[kk * 132 + tx * 8 + 4];
#pragma unroll
            for (int i = 0; i < 8; i++)
#pragma unroll
                for (int j = 0; j < 8; j++) acc[i][j] = fmaf(a[i], b[j], acc[i][j]);
        }
        __syncthreads();
    }
#pragma unroll
    for (int i = 0; i < 8; i++) {
        int row = ty * 8 + i;
        float4 o0 = make_float4(acc[i][0], acc[i][1], acc[i][2], acc[i][3]);
        float4 o1 = make_float4(acc[i][4], acc[i][5], acc[i][6], acc[i][7]);
        *(float4*)&g_Wf[g * 16384 + row * 128 + tx * 8]     = o0;
        *(float4*)&g_Wf[g * 16384 + row * 128 + tx * 8 + 4] = o1;
    }
}

// ---------------- TF32 tensor-core GEMM: hws = relu(A + bias) @ B * dinv[row] ----------------
// epilogue stores fp16 into g_hwsh
__global__ __launch_bounds__(256, 2) void gemm_tc_k(
    const float* __restrict__ Aext, const float* __restrict__ Bext,
    const float* __restrict__ bias, int useAcc, int perGroupB)
{
    __shared__ __align__(16) float As[128 * 36];
    __shared__ __align__(16) float Bs[32 * 132];
    int tid = threadIdx.x;
    int m0 = blockIdx.x * 128;
    const float* A = useAcc ? g_acc : Aext;
    const float* B = perGroupB ? (g_Wf + (m0 >> 11) * (FH * FH)) : Bext;
    int wid = tid >> 5, lane = tid & 31;
    int g = lane >> 2, t = lane & 3;

    float c[16][4];
#pragma unroll
    for (int nt = 0; nt < 16; nt++)
#pragma unroll
        for (int j = 0; j < 4; j++) c[nt][j] = 0.f;

#pragma unroll 1
    for (int k0 = 0; k0 < 128; k0 += 32) {
#pragma unroll
        for (int it = 0; it < 4; it++) {
            int i = it * 256 + tid;
            int r = i >> 3, c4 = (i & 7) * 4;
            float4 v = *(const float4*)&A[(size_t)(m0 + r) * FH + k0 + c4];
            if (bias) {
                float4 bb = *(const float4*)&bias[k0 + c4];
                v.x = fmaxf(v.x + bb.x, 0.f);
                v.y = fmaxf(v.y + bb.y, 0.f);
                v.z = fmaxf(v.z + bb.z, 0.f);
                v.w = fmaxf(v.w + bb.w, 0.f);
            }
            As[r * 36 + c4 + 0] = __uint_as_float(tf32r(v.x));
            As[r * 36 + c4 + 1] = __uint_as_float(tf32r(v.y));
            As[r * 36 + c4 + 2] = __uint_as_float(tf32r(v.z));
            As[r * 36 + c4 + 3] = __uint_as_float(tf32r(v.w));
        }
#pragma unroll
        for (int it = 0; it < 4; it++) {
            int i = it * 256 + tid;
            int r = i >> 5, cc = (i & 31) * 4;
            float4 v = *(const float4*)&B[(k0 + r) * FH + cc];
            Bs[r * 132 + cc + 0] = __uint_as_float(tf32r(v.x));
            Bs[r * 132 + cc + 1] = __uint_as_float(tf32r(v.y));
            Bs[r * 132 + cc + 2] = __uint_as_float(tf32r(v.z));
            Bs[r * 132 + cc + 3] = __uint_as_float(tf32r(v.w));
        }
        __syncthreads();
#pragma unroll
        for (int kk = 0; kk < 32; kk += 8) {
            int ar = (wid * 16 + g) * 36 + kk + t;
            unsigned a0 = __float_as_uint(As[ar]);
            unsigned a1 = __float_as_uint(As[ar + 8 * 36]);
            unsigned a2 = __float_as_uint(As[ar + 4]);
            unsigned a3 = __float_as_uint(As[ar + 8 * 36 + 4]);
#pragma unroll
            for (int nt = 0; nt < 16; nt++) {
                unsigned b0 = __float_as_uint(Bs[(kk + t) * 132 + nt * 8 + g]);
                unsigned b1 = __float_as_uint(Bs[(kk + t + 4) * 132 + nt * 8 + g]);
                asm volatile(
                    "mma.sync.aligned.m16n8k8.row.col.f32.tf32.tf32.f32 "
                    "{%0,%1,%2,%3}, {%4,%5,%6,%7}, {%8,%9}, {%0,%1,%2,%3};"
                    : "+f"(c[nt][0]), "+f"(c[nt][1]), "+f"(c[nt][2]), "+f"(c[nt][3])
                    : "r"(a0), "r"(a1), "r"(a2), "r"(a3), "r"(b0), "r"(b1));
            }
        }
        __syncthreads();
    }

    int r0 = m0 + wid * 16 + g;
    float d0 = g_dinv[r0];
    float d1 = g_dinv[r0 + 8];
#pragma unroll
    for (int nt = 0; nt < 16; nt++) {
        int col = nt * 8 + 2 * t;
        *(__half2*)&g_hwsh[(size_t)r0 * FH + col] =
            __floats2half2_rn(c[nt][0] * d0, c[nt][1] * d0);
        *(__half2*)&g_hwsh[(size_t)(r0 + 8) * FH + col] =
            __floats2half2_rn(c[nt][2] * d1, c[nt][3] * d1);
    }
}

// ---------------- CSR aggregate: acc[n] = dinv[n]*(hws[n] + sum_src hws[src]) ----------------
// hws stored fp16 (256 B/node); warp per node, lane covers 4 cols (uint2 = 4 halves)
__global__ __launch_bounds__(256) void agg_k() {
    int warp = (blockIdx.x * 256 + threadIdx.x) >> 5;
    int lane = threadIdx.x & 31;
    const uint2* hv = (const uint2*)g_hwsh;
    uint2 u = hv[(size_t)warp * 32 + lane];   // self loop term
    float2 f0 = __half22float2(*(__half2*)&u.x);
    float2 f1 = __half22float2(*(__half2*)&u.y);
    float4 a = make_float4(f0.x, f0.y, f1.x, f1.y);
    int s0 = g_rowstart[warp];
    int dn = g_deg[warp];
    int e = 0;
    for (; e + 2 <= dn; e += 2) {
        int i1 = g_sorted[s0 + e];
        int i2 = g_sorted[s0 + e + 1];
        uint2 u1 = hv[(size_t)i1 * 32 + lane];
        uint2 u2 = hv[(size_t)i2 * 32 + lane];
        float2 a0 = __half22float2(*(__half2*)&u1.x);
        float2 a1 = __half22float2(*(__half2*)&u1.y);
        float2 b0 = __half22float2(*(__half2*)&u2.x);
        float2 b1 = __half22float2(*(__half2*)&u2.y);
        a.x += a0.x + b0.x; a.y += a0.y + b0.y;
        a.z += a1.x + b1.x; a.w += a1.y + b1.y;
    }
    if (e < dn) {
        int i1 = g_sorted[s0 + e];
        uint2 u1 = hv[(size_t)i1 * 32 + lane];
        float2 a0 = __half22float2(*(__half2*)&u1.x);
        float2 a1 = __half22float2(*(__half2*)&u1.y);
        a.x += a0.x; a.y += a0.y; a.z += a1.x; a.w += a1.y;
    }
    float d = g_dinv[warp];
    a.x *= d; a.y *= d; a.z *= d; a.w *= d;
    ((float4*)g_acc)[(size_t)warp * 32 + lane] = a;
}

// ---------------- logits + log_softmax (32 nodes per block) ----------------
__global__ __launch_bounds__(256) void logits_k(
    const float* __restrict__ bias, const float* __restrict__ W,
    const float* __restrict__ lb, float* __restrict__ out)
{
    __shared__ __align__(16) float Ws[64 * 129];   // padded rows; rows 40..63 zeroed
    __shared__ __align__(16) float Hs[8 * 128];
    int tid = threadIdx.x;
    for (int i = tid; i < CC * 128; i += 256) {
        int cI = i >> 7, k = i & 127;
        Ws[cI * 129 + k] = W[i];
    }
    for (int i = CC * 128 + tid; i < 64 * 128; i += 256) {
        int cI = i >> 7, k = i & 127;
        Ws[cI * 129 + k] = 0.f;
    }
    __syncthreads();
    int wl = tid >> 5;
    int lane = tid & 31;
    float4 bb = ((const float4*)bias)[lane];
    float lb0 = lb[lane];
    float lb1 = (lane < 8) ? lb[32 + lane] : 0.f;
    const float* hrow = &Hs[wl * 128];
    const float* wr0 = &Ws[lane * 129];
    const float* wr1 = &Ws[(32 + lane) * 129];

#pragma unroll 1
    for (int rep = 0; rep < 4; rep++) {
        int node = blockIdx.x * 32 + wl * 4 + rep;
        float4 h = ((const float4*)g_acc)[(size_t)node * 32 + lane];
        h.x = fmaxf(h.x + bb.x, 0.f);
        h.y = fmaxf(h.y + bb.y, 0.f);
        h.z = fmaxf(h.z + bb.z, 0.f);
        h.w = fmaxf(h.w + bb.w, 0.f);
        *(float4*)&Hs[wl * 128 + lane * 4] = h;
        __syncwarp();
        float s0 = lb0;
        float s1 = lb1;
#pragma unroll 8
        for (int k = 0; k < 128; k++) {
            float hvv = hrow[k];
            s0 = fmaf(hvv, wr0[k], s0);
            s1 = fmaf(hvv, wr1[k], s1);
        }
        float m = (lane < 8) ? fmaxf(s0, s1) : s0;
#pragma unroll
        for (int off = 16; off; off >>= 1) m = fmaxf(m, __shfl_xor_sync(0xffffffffu, m, off));
        float e0 = expf(s0 - m);
        float e1 = (lane < 8) ? expf(s1 - m) : 0.f;
        float es = e0 + e1;
#pragma unroll
        for (int off = 16; off; off >>= 1) es += __shfl_xor_sync(0xffffffffu, es, off);
        float lse = m + logf(es);
        out[(size_t)node * CC + lane] = s0 - lse;
        if (lane < 8) out[(size_t)node * CC + 32 + lane] = s1 - lse;
        __syncwarp();
    }
}

// ---------------- launch ----------------
extern "C" void kernel_launch(void* const* d_in, const int* in_sizes, int n_in,
                              void* d_out, int out_size) {
    const float* x     = (const float*)d_in[0];
    const void*  ei    = d_in[1];
    const float* Em    = (const float*)d_in[2];
    const float* w0    = (const float*)d_in[4];
    const float* b0    = (const float*)d_in[5];
    const float* convw = (const float*)d_in[6];
    const float* convb = (const float*)d_in[7];
    const float* ltw   = (const float*)d_in[8];
    const float* ltb   = (const float*)d_in[9];
    float* out = (float*)d_out;
    int E = in_sizes[1] / 2;

    // edge dtype sniff (int32 vs int64) + normalize + degree count
    detect_k<<<1, 32>>>((const unsigned long long*)ei);
    zero_deg_k<<<NN / 256, 256>>>();
    conv_count_k<<<(E + 255) / 256, 256>>>(ei, E);
    scan1_k<<<NN / 256, 256>>>();
    scan2_k<<<1, 256>>>();
    scan3_k<<<NN / 256, 256>>>();
    sort_k<<<(E + 255) / 256, 256>>>(E);

    // Wfused = relu(w0*E_meta + b0) @ conv_w[0]
    wdyn_fuse_k<<<GG, 256>>>(w0, Em, b0, convw);

    // layer 1: hw1 = x @ Wfused[g], scaled by dinv
    gemm_tc_k<<<NN / 128, 256>>>(x, nullptr, nullptr, 0, 1);
    agg_k<<<NN / 8, 256>>>();
    // layer 2: hw2 = relu(acc + b0) @ W2
    gemm_tc_k<<<NN / 128, 256>>>(nullptr, convw + 1 * FH * FH, convb + 0 * FH, 1, 0);
    agg_k<<<NN / 8, 256>>>();
    // layer 3: hw3 = relu(acc + b1) @ W3
    gemm_tc_k<<<NN / 128, 256>>>(nullptr, convw + 2 * FH * FH, convb + 1 * FH, 1, 0);
    agg_k<<<NN / 8, 256>>>();
    // logits + log_softmax from relu(acc + b2)
    logits_k<<<NN / 32, 256>>>(convb + 2 * FH, ltw, ltb, out);
}